// round 15
// baseline (speedup 1.0000x reference)
#include <cuda_runtime.h>
#include <cstdint>

#define M_DIM 512
#define K_DIM 256
#define O_DIM 256
#define BK 64
#define KSPLIT 4
#define RBLK 128          /* reduce blocks */
#define SP 68             /* smem row stride (floats): 64 + 4 pad */

#define BIGF  12582912.0f          /* 1.5 * 2^23 */
#define BIGU  0x4B400000u
#define THETA 0.0009765625f        /* 2^-10 */
#define EPSB  0.000244140625f      /* 2^-12 */

// ---------------- device scratch (no allocations allowed) ----------------
__device__ float2 g_bmax2[RBLK];                  // per-block (max|x|, max(|W|,|b|))
__device__ int    g_part[KSPLIT][M_DIM * O_DIM];  // exact per-chunk partial sums
__device__ unsigned g_cnt[(M_DIM / 32) * (O_DIM / 32)];  // tile arrival counters (=0)

// ---------------- helpers ----------------
__device__ __forceinline__ float san(float v) {
    if (isnan(v)) return 0.0f;
    if (isinf(v)) return 1.0f;
    return v;
}

// sn = 2^floor(log2(floor(32/mx))); argument of log2 is a positive integer.
__device__ __forceinline__ float calc_sn(float mx) {
    if (mx == 0.0f) mx = 1.0f;
    float r = floorf(32.0f / mx);
    return ldexpf(1.0f, ilogbf(r));
}

// block-level max reduce of (mx, md) over 256 threads; result valid in ALL threads
__device__ __forceinline__ float2 block_max2(float mx, float md) {
    __shared__ float2 s_red[8];
    __shared__ float2 s_out;
    #pragma unroll
    for (int off = 16; off; off >>= 1) {
        mx = fmaxf(mx, __shfl_xor_sync(0xFFFFFFFFu, mx, off));
        md = fmaxf(md, __shfl_xor_sync(0xFFFFFFFFu, md, off));
    }
    if ((threadIdx.x & 31) == 0) s_red[threadIdx.x >> 5] = make_float2(mx, md);
    __syncthreads();
    if (threadIdx.x == 0) {
        float2 r = s_red[0];
        #pragma unroll
        for (int w = 1; w < 8; w++) {
            r.x = fmaxf(r.x, s_red[w].x);
            r.y = fmaxf(r.y, s_red[w].y);
        }
        s_out = r;
    }
    __syncthreads();
    return s_out;
}

// ---------------- pass 1: per-block maxima (grid-stride, no tail) ----------------
__global__ __launch_bounds__(256) void reduce_kernel(const float* __restrict__ x,
                                                     const float* __restrict__ W,
                                                     const float* __restrict__ b) {
    float mx = 0.0f, md = 0.0f;
    int t = blockIdx.x * 256 + threadIdx.x;
    const int stride = RBLK * 256;
    for (int i = t; i < M_DIM * K_DIM; i += stride) mx = fmaxf(mx, fabsf(san(x[i])));
    for (int i = t; i < O_DIM * K_DIM; i += stride) md = fmaxf(md, fabsf(san(W[i])));
    md = fmaxf(md, fabsf(san(b[threadIdx.x])));   // 256 threads cover b exactly
    float2 r = block_max2(mx, md);
    if (threadIdx.x == 0) g_bmax2[blockIdx.x] = r;
}

// ---------------- pass 2: fused quantize + K-split LUT-GEMM + in-kernel epilogue
// grid (8 o-blk, 16 m-blk, KSPLIT=4) = 512 blocks, 4 CTA/SM (64-reg budget).
// Tile 32m x 32o x 64k, 256 threads, 2x2 outputs/thread. Row-major smem
// [row][k] (stride 68): mainloop = 4 LDS.128 + 16 FFMA.RD per 4 k's.
__global__ __launch_bounds__(256, 4) void fused_kernel(const float* __restrict__ x,
                                                       const float* __restrict__ W,
                                                       const float* __restrict__ b,
                                                       float* __restrict__ out) {
    __shared__ float s_a[32][SP];   // [m][k], float(trunc_RN(x*sn2)) + 2^-10
    __shared__ float s_u[32][SP];   // [o][k], +/-|bb|/32 (- 2^-12 if bb<0)
    __shared__ int   s_neg[32];     // per local-o count of bb<0 in this k-chunk
    __shared__ int   s_last;

    // prologue: finalize global maxima -> sn1, sn2 (all threads)
    float mx = 0.0f, md = 0.0f;
    if (threadIdx.x < RBLK) {
        float2 v = g_bmax2[threadIdx.x];
        mx = v.x; md = v.y;
    }
    float2 r = block_max2(mx, md);
    float sn2 = calc_sn(r.x);
    float sn1 = calc_sn(r.y);
    float inv1 = 1.0f / sn1, inv2 = 1.0f / sn2;   // exact (pow-2)

    int m0 = blockIdx.y * 32;
    int o0 = blockIdx.x * 32;
    int kc = blockIdx.z * BK;
    int mm = threadIdx.x >> 3;          // staging row (m for x, o for W)
    int kg = (threadIdx.x & 7) << 3;    // staging k-offset (8 floats)

    // stage + conversion-free quantize (LDG.128 in, STS.128 out, no transpose)
    int negcnt = 0;
    {
        const float4* pa = (const float4*)&x[(m0 + mm) * K_DIM + kc + kg];
        const float4* pw = (const float4*)&W[(o0 + mm) * K_DIM + kc + kg];
        float4 aIn[2] = {pa[0], pa[1]};
        float4 wIn[2] = {pw[0], pw[1]};
        float aq[8], uq[8];
        #pragma unroll
        for (int h = 0; h < 2; h++) {
            float av[4] = {aIn[h].x, aIn[h].y, aIn[h].z, aIn[h].w};
            float wv[4] = {wIn[h].x, wIn[h].y, wIn[h].z, wIn[h].w};
            #pragma unroll
            for (int e = 0; e < 4; e++) {
                // x: t = RN(x*sn2) >= 0 ; floor(t) exactly via FADD.RD magic
                float t  = san(av[4 * h + e - 4 * h + e]) ; // (identity; keep simple below)
                t = san(av[e]) * sn2;
                float fl = __fadd_rd(t, BIGF) - BIGF;
                aq[4 * h + e] = fl + THETA;
                // W: tw = RN(w*sn1) ; |bb| = floor(|tw|) ; sign/EPSB via selects
                float tw = san(wv[e]) * sn1;
                float ab = __fadd_rd(fabsf(tw), BIGF) - BIGF;
                bool  isneg = (tw < 0.0f) && (ab > 0.0f);
                float us = ab * (1.0f / 32.0f);
                us = (tw < 0.0f) ? -us : us;
                if (isneg) { us -= EPSB; negcnt++; }
                uq[4 * h + e] = us;
            }
        }
        *reinterpret_cast<float4*>(&s_a[mm][kg])     = make_float4(aq[0], aq[1], aq[2], aq[3]);
        *reinterpret_cast<float4*>(&s_a[mm][kg + 4]) = make_float4(aq[4], aq[5], aq[6], aq[7]);
        *reinterpret_cast<float4*>(&s_u[mm][kg])     = make_float4(uq[0], uq[1], uq[2], uq[3]);
        *reinterpret_cast<float4*>(&s_u[mm][kg + 4]) = make_float4(uq[4], uq[5], uq[6], uq[7]);
    }
    // per-o negative count over this chunk (8 consecutive lanes share row mm)
    #pragma unroll
    for (int off = 1; off < 8; off <<= 1)
        negcnt += __shfl_xor_sync(0xFFFFFFFFu, negcnt, off);
    if ((threadIdx.x & 7) == 0) s_neg[mm] = negcnt;
    __syncthreads();

    int tx = threadIdx.x & 15;      // o
    int ty = threadIdx.x >> 4;      // m

    // float accumulator chains: integer-valued, stay in [2^23, 2^24).
    // Each FFMA.RD adds exactly floor(a'*u') to the chain.
    float f00 = BIGF, f01 = BIGF, f10 = BIGF, f11 = BIGF;

    #pragma unroll 8
    for (int k = 0; k < BK; k += 4) {
        float4 a0 = *reinterpret_cast<const float4*>(&s_a[2 * ty][k]);      // broadcast
        float4 a1 = *reinterpret_cast<const float4*>(&s_a[2 * ty + 1][k]);  // broadcast
        float4 u0 = *reinterpret_cast<const float4*>(&s_u[2 * tx][k]);      // conflict-free
        float4 u1 = *reinterpret_cast<const float4*>(&s_u[2 * tx + 1][k]);  // conflict-free
        f00 = __fmaf_rd(a0.x, u0.x, f00); f00 = __fmaf_rd(a0.y, u0.y, f00);
        f00 = __fmaf_rd(a0.z, u0.z, f00); f00 = __fmaf_rd(a0.w, u0.w, f00);
        f01 = __fmaf_rd(a0.x, u1.x, f01); f01 = __fmaf_rd(a0.y, u1.y, f01);
        f01 = __fmaf_rd(a0.z, u1.z, f01); f01 = __fmaf_rd(a0.w, u1.w, f01);
        f10 = __fmaf_rd(a1.x, u0.x, f10); f10 = __fmaf_rd(a1.y, u0.y, f10);
        f10 = __fmaf_rd(a1.z, u0.z, f10); f10 = __fmaf_rd(a1.w, u0.w, f10);
        f11 = __fmaf_rd(a1.x, u1.x, f11); f11 = __fmaf_rd(a1.y, u1.y, f11);
        f11 = __fmaf_rd(a1.z, u1.z, f11); f11 = __fmaf_rd(a1.w, u1.w, f11);
    }

    // exact per-chunk partial: S = bits(f) - BIGU, plus chunk negative count
    int m = m0 + 2 * ty;
    int o = o0 + 2 * tx;
    int n0 = s_neg[2 * tx], n1 = s_neg[2 * tx + 1];
    int* __restrict__ p = g_part[blockIdx.z];
    *reinterpret_cast<int2*>(&p[m * O_DIM + o]) =
        make_int2((int)(__float_as_uint(f00) - BIGU) + n0,
                  (int)(__float_as_uint(f01) - BIGU) + n1);
    *reinterpret_cast<int2*>(&p[(m + 1) * O_DIM + o]) =
        make_int2((int)(__float_as_uint(f10) - BIGU) + n0,
                  (int)(__float_as_uint(f11) - BIGU) + n1);

    // ---- last-block-does-epilogue (arrive-and-exit; no waiting) ----
    __syncthreads();                       // all partial stores issued
    int tile = blockIdx.y * (O_DIM / 32) + blockIdx.x;
    if (threadIdx.x == 0) {
        __threadfence();                   // make partials visible chip-wide
        unsigned old = atomicAdd(&g_cnt[tile], 1u);
        s_last = (old == KSPLIT - 1);
        if (old == KSPLIT - 1) g_cnt[tile] = 0u;   // reset for next graph replay
    }
    __syncthreads();
    if (s_last) {
        __threadfence();                   // acquire other blocks' partials
        #pragma unroll
        for (int j = 0; j < 4; j++) {
            int e = threadIdx.x + 256 * j;         // 0..1023 within tile
            int ml = e >> 5, ol = e & 31;
            int idx = (m0 + ml) * O_DIM + o0 + ol;
            int x9 = g_part[0][idx] + g_part[1][idx]
                   + g_part[2][idx] + g_part[3][idx];
            int cc = (int)(san(b[o0 + ol]) * sn1);
            // d = trunc(x9 * 1/sn2) + cc ; out = d * 1/sn1 (all exact pow-2)
            int d = (int)((float)x9 * inv2) + cc;
            out[idx] = (float)d * inv1;
        }
    }
}

// ---------------- launch ----------------
extern "C" void kernel_launch(void* const* d_in, const int* in_sizes, int n_in,
                              void* d_out, int out_size) {
    (void)in_sizes; (void)n_in; (void)out_size;
    const float* x = (const float*)d_in[0];
    const float* W = (const float*)d_in[1];
    const float* b = (const float*)d_in[2];
    // d_in[3] (lut) unused: lut[i][j] == floor(i*j/32), reproduced exactly by
    // chained FFMA.RD magic-floor accumulation.

    reduce_kernel<<<RBLK, 256>>>(x, W, b);
    dim3 grid(O_DIM / 32, M_DIM / 32, KSPLIT);
    fused_kernel<<<grid, 256>>>(x, W, b, (float*)d_out);
}

// round 16
// speedup vs baseline: 1.1791x; 1.1791x over previous
#include <cuda_runtime.h>
#include <cstdint>

#define M_DIM 512
#define K_DIM 256
#define O_DIM 256
#define BK 64
#define KSPLIT 4
#define NBLK 512          /* total blocks; <= 4 CTA/SM * 148 SM = 592 -> co-resident */

#define BIGF  12582912.0f          /* 1.5 * 2^23 */
#define BIGU  0x4B400000u
#define THETA 0.0009765625f        /* 2^-10 */
#define EPSB  0.000244140625f      /* 2^-12 */

// ---------------- device scratch (no allocations; all zero-init) ----------------
__device__ unsigned g_amax_bits;                  // bits of max |x|
__device__ unsigned g_dmax_bits;                  // bits of max(|W|,|b|)
__device__ unsigned g_arrive;                     // grid-barrier arrivals
__device__ unsigned g_readcnt;                    // post-barrier readers (for reset)
__device__ int    g_part[KSPLIT][M_DIM * O_DIM];  // exact per-chunk partial sums
__device__ unsigned g_cnt[(M_DIM / 32) * (O_DIM / 32)];  // tile arrival counters

// ---------------- helpers ----------------
__device__ __forceinline__ float san(float v) {
    if (isnan(v)) return 0.0f;
    if (isinf(v)) return 1.0f;
    return v;
}

// sn = 2^floor(log2(floor(32/mx))); argument of log2 is a positive integer.
__device__ __forceinline__ float calc_sn(float mx) {
    if (mx == 0.0f) mx = 1.0f;
    float r = floorf(32.0f / mx);
    return ldexpf(1.0f, ilogbf(r));
}

// ---------------- THE kernel: reduce + barrier + quantize + GEMM + epilogue ----
// grid (8 o-blk, 16 m-blk, KSPLIT=4) = 512 blocks, 256 threads.
// launch_bounds(256,4): regs<=64, smem 18KB -> >=4 CTA/SM guaranteed, so all
// 512 blocks are co-resident and the spin barrier cannot deadlock.
__global__ __launch_bounds__(256, 4) void mono_kernel(const float* __restrict__ x,
                                                      const float* __restrict__ W,
                                                      const float* __restrict__ b,
                                                      float* __restrict__ out) {
    __shared__ float  s_a[BK][34];   // [k][m]  (proven R13 layout)
    __shared__ float  s_u[BK][34];   // [k][o]
    __shared__ int    s_neg[32];     // per local-o count of bb<0 in this k-chunk
    __shared__ int    s_last;
    __shared__ float2 s_red[8];
    __shared__ float2 s_sn;          // {sn1, sn2}

    int tid = threadIdx.x;
    int m0 = blockIdx.y * 32;
    int o0 = blockIdx.x * 32;
    int kc = blockIdx.z * BK;
    int mm = tid >> 3;               // staging row (m for x, o for W)
    int kg = (tid & 7) << 3;         // staging k-offset (8 floats)

    // ---- prefetch this block's tiles NOW (sn-independent); latency hides
    // under the max-reduce + grid barrier below.
    const float4* pa = (const float4*)&x[(m0 + mm) * K_DIM + kc + kg];
    const float4* pw = (const float4*)&W[(o0 + mm) * K_DIM + kc + kg];
    float4 aIn0 = pa[0], aIn1 = pa[1];
    float4 wIn0 = pw[0], wIn1 = pw[1];

    // ---- phase 1: global maxima, 1/512 slice per block ----
    int fid = blockIdx.x + 8 * blockIdx.y + 128 * blockIdx.z;   // 0..511
    float mx = fabsf(san(x[fid * 256 + tid]));                  // covers x exactly
    float md = 0.0f;
    if (fid < 256)       md = fabsf(san(W[fid * 256 + tid]));   // covers W exactly
    else if (fid == 256) md = fabsf(san(b[tid]));               // covers b exactly
    #pragma unroll
    for (int off = 16; off; off >>= 1) {
        mx = fmaxf(mx, __shfl_xor_sync(0xFFFFFFFFu, mx, off));
        md = fmaxf(md, __shfl_xor_sync(0xFFFFFFFFu, md, off));
    }
    if ((tid & 31) == 0) s_red[tid >> 5] = make_float2(mx, md);
    __syncthreads();

    // ---- grid barrier + sn broadcast (thread 0 only spins; co-residency
    // guaranteed, so this cannot deadlock) ----
    if (tid == 0) {
        float2 r = s_red[0];
        #pragma unroll
        for (int w = 1; w < 8; w++) {
            r.x = fmaxf(r.x, s_red[w].x);
            r.y = fmaxf(r.y, s_red[w].y);
        }
        atomicMax(&g_amax_bits, __float_as_uint(r.x));
        atomicMax(&g_dmax_bits, __float_as_uint(r.y));
        __threadfence();
        atomicAdd(&g_arrive, 1u);
        while (*(volatile unsigned*)&g_arrive < NBLK) __nanosleep(64);
        __threadfence();
        unsigned ab = atomicAdd(&g_amax_bits, 0u);   // L2-coherent read
        unsigned db = atomicAdd(&g_dmax_bits, 0u);
        s_sn = make_float2(calc_sn(__uint_as_float(db)),    // sn1
                           calc_sn(__uint_as_float(ab)));   // sn2
        unsigned old = atomicAdd(&g_readcnt, 1u);
        if (old == NBLK - 1u) {      // all blocks have read -> reset for replay
            g_amax_bits = 0u; g_dmax_bits = 0u;
            g_arrive = 0u;   g_readcnt = 0u;
        }
    }
    __syncthreads();
    float sn1 = s_sn.x, sn2 = s_sn.y;
    float inv1 = 1.0f / sn1, inv2 = 1.0f / sn2;   // exact (pow-2)

    // ---- phase 2: conversion-free quantize of prefetched tiles (R13-exact) ----
    int negcnt = 0;
    {
        float4 aIn[2] = {aIn0, aIn1};
        float4 wIn[2] = {wIn0, wIn1};
        #pragma unroll
        for (int h = 0; h < 2; h++) {
            float av[4] = {aIn[h].x, aIn[h].y, aIn[h].z, aIn[h].w};
            float wv[4] = {wIn[h].x, wIn[h].y, wIn[h].z, wIn[h].w};
            #pragma unroll
            for (int e = 0; e < 4; e++) {
                int j = 4 * h + e;
                // x: t = RN(x*sn2) >= 0 ; floor(t) exactly via FADD.RD magic
                float t  = san(av[e]) * sn2;
                float fl = __fadd_rd(t, BIGF) - BIGF;
                s_a[kg + j][mm] = fl + THETA;
                // W: tw = RN(w*sn1) ; |bb| = floor(|tw|) ; sign/EPSB via selects
                float tw = san(wv[e]) * sn1;
                float ab2 = __fadd_rd(fabsf(tw), BIGF) - BIGF;
                bool  isneg = (tw < 0.0f) && (ab2 > 0.0f);
                float us = ab2 * (1.0f / 32.0f);
                us = (tw < 0.0f) ? -us : us;
                if (isneg) { us -= EPSB; negcnt++; }
                s_u[kg + j][mm] = us;
            }
        }
    }
    // per-o negative count over this chunk (8 consecutive lanes share row mm)
    #pragma unroll
    for (int off = 1; off < 8; off <<= 1)
        negcnt += __shfl_xor_sync(0xFFFFFFFFu, negcnt, off);
    if ((tid & 7) == 0) s_neg[mm] = negcnt;
    __syncthreads();

    int tx = tid & 15;      // o
    int ty = tid >> 4;      // m

    // float accumulator chains: integer-valued, stay in [2^23, 2^24).
    // Each FFMA.RD adds exactly floor(a'*u') to the chain.
    float f00 = BIGF, f01 = BIGF, f10 = BIGF, f11 = BIGF;

    #pragma unroll 16
    for (int k = 0; k < BK; k++) {
        float2 a2 = *reinterpret_cast<const float2*>(&s_a[k][2 * ty]);
        float2 u2 = *reinterpret_cast<const float2*>(&s_u[k][2 * tx]);
        f00 = __fmaf_rd(a2.x, u2.x, f00);
        f01 = __fmaf_rd(a2.x, u2.y, f01);
        f10 = __fmaf_rd(a2.y, u2.x, f10);
        f11 = __fmaf_rd(a2.y, u2.y, f11);
    }

    // exact per-chunk partial: S = bits(f) - BIGU, plus chunk negative count
    int m = m0 + 2 * ty;
    int o = o0 + 2 * tx;
    int n0 = s_neg[2 * tx], n1 = s_neg[2 * tx + 1];
    int* __restrict__ p = g_part[blockIdx.z];
    *reinterpret_cast<int2*>(&p[m * O_DIM + o]) =
        make_int2((int)(__float_as_uint(f00) - BIGU) + n0,
                  (int)(__float_as_uint(f01) - BIGU) + n1);
    *reinterpret_cast<int2*>(&p[(m + 1) * O_DIM + o]) =
        make_int2((int)(__float_as_uint(f10) - BIGU) + n0,
                  (int)(__float_as_uint(f11) - BIGU) + n1);

    // ---- last-block-does-epilogue (arrive-and-exit; no waiting) ----
    __syncthreads();                       // all partial stores issued
    int tile = blockIdx.y * (O_DIM / 32) + blockIdx.x;
    if (tid == 0) {
        __threadfence();                   // make partials visible chip-wide
        unsigned old = atomicAdd(&g_cnt[tile], 1u);
        s_last = (old == KSPLIT - 1);
        if (old == KSPLIT - 1) g_cnt[tile] = 0u;   // reset for next graph replay
    }
    __syncthreads();
    if (s_last) {
        __threadfence();                   // acquire other blocks' partials
        #pragma unroll
        for (int j = 0; j < 4; j++) {
            int e = tid + 256 * j;                 // 0..1023 within tile
            int ml = e >> 5, ol = e & 31;
            int idx = (m0 + ml) * O_DIM + o0 + ol;
            int x9 = g_part[0][idx] + g_part[1][idx]
                   + g_part[2][idx] + g_part[3][idx];
            int cc = (int)(san(b[o0 + ol]) * sn1);
            // d = trunc(x9 * 1/sn2) + cc ; out = d * 1/sn1 (all exact pow-2)
            int d = (int)((float)x9 * inv2) + cc;
            out[idx] = (float)d * inv1;
        }
    }
}

// ---------------- launch: ONE kernel ----------------
extern "C" void kernel_launch(void* const* d_in, const int* in_sizes, int n_in,
                              void* d_out, int out_size) {
    (void)in_sizes; (void)n_in; (void)out_size;
    const float* x = (const float*)d_in[0];
    const float* W = (const float*)d_in[1];
    const float* b = (const float*)d_in[2];
    // d_in[3] (lut) unused: lut[i][j] == floor(i*j/32), reproduced exactly by
    // chained FFMA.RD magic-floor accumulation.

    dim3 grid(O_DIM / 32, M_DIM / 32, KSPLIT);   // 512 blocks = one wave
    mono_kernel<<<grid, 256>>>(x, W, b, (float*)d_out);
}

// round 17
// speedup vs baseline: 1.8136x; 1.5381x over previous
#include <cuda_runtime.h>
#include <cstdint>

#define M_DIM 512
#define K_DIM 256
#define O_DIM 256
#define BK 64
#define RBLK 128          /* reduce blocks */

#define BIGF  12582912.0f          /* 1.5 * 2^23 */
#define BIGU  0x4B400000u
#define THETA 0.0009765625f        /* 2^-10 */
#define EPSB  0.000244140625f      /* 2^-12 */

// ---------------- device scratch (no allocations allowed) ----------------
__device__ float2 g_bmax2[RBLK];   // per-block (max|x|, max(|W|,|b|))

// ---------------- helpers ----------------
__device__ __forceinline__ float san(float v) {
    if (isnan(v)) return 0.0f;
    if (isinf(v)) return 1.0f;
    return v;
}

// sn = 2^floor(log2(floor(32/mx))); argument of log2 is a positive integer.
__device__ __forceinline__ float calc_sn(float mx) {
    if (mx == 0.0f) mx = 1.0f;
    float r = floorf(32.0f / mx);
    return ldexpf(1.0f, ilogbf(r));
}

// block-level max reduce of (mx, md) over 256 threads; result valid in ALL threads
__device__ __forceinline__ float2 block_max2(float mx, float md) {
    __shared__ float2 s_red[8];
    __shared__ float2 s_out;
    #pragma unroll
    for (int off = 16; off; off >>= 1) {
        mx = fmaxf(mx, __shfl_xor_sync(0xFFFFFFFFu, mx, off));
        md = fmaxf(md, __shfl_xor_sync(0xFFFFFFFFu, md, off));
    }
    if ((threadIdx.x & 31) == 0) s_red[threadIdx.x >> 5] = make_float2(mx, md);
    __syncthreads();
    if (threadIdx.x == 0) {
        float2 r = s_red[0];
        #pragma unroll
        for (int w = 1; w < 8; w++) {
            r.x = fmaxf(r.x, s_red[w].x);
            r.y = fmaxf(r.y, s_red[w].y);
        }
        s_out = r;
    }
    __syncthreads();
    return s_out;
}

// ---------------- pass 1: per-block maxima (grid-stride; R7-exact) ----------------
__global__ __launch_bounds__(256) void reduce_kernel(const float* __restrict__ x,
                                                     const float* __restrict__ W,
                                                     const float* __restrict__ b) {
    float mx = 0.0f, md = 0.0f;
    int t = blockIdx.x * 256 + threadIdx.x;
    const int stride = RBLK * 256;
    for (int i = t; i < M_DIM * K_DIM; i += stride) mx = fmaxf(mx, fabsf(san(x[i])));
    for (int i = t; i < O_DIM * K_DIM; i += stride) md = fmaxf(md, fabsf(san(W[i])));
    md = fmaxf(md, fabsf(san(b[threadIdx.x])));   // 256 threads cover b exactly
    float2 r = block_max2(mx, md);
    if (threadIdx.x == 0) g_bmax2[blockIdx.x] = r;
}

// ---------------- pass 2: fused quantize + LUT-GEMM + epilogue (R7 structure) ---
// grid (8 o-blk, 16 m-blk) = 128 blocks; tile 32m x 32o, full K=256 in 4 smem
// stages; 256 threads, 2x2 outputs/thread. Conversion-free quantize (R13),
// chained FFMA.RD accumulation (R11): 1 FFMA per MAC, no integer adds.
__global__ __launch_bounds__(256) void fused_kernel(const float* __restrict__ x,
                                                    const float* __restrict__ W,
                                                    const float* __restrict__ b,
                                                    float* __restrict__ out) {
    __shared__ float s_a[BK][34];   // [k][m], float(trunc_RN(x*sn2)) + 2^-10
    __shared__ float s_u[BK][34];   // [k][o], +/-|bb|/32 (- 2^-12 if bb<0)
    __shared__ int   s_neg[32];     // per local-o count of bb<0 over full K

    // prologue: finalize global maxima -> sn1, sn2 (all threads)
    float mx = 0.0f, md = 0.0f;
    if (threadIdx.x < RBLK) {
        float2 v = g_bmax2[threadIdx.x];
        mx = v.x; md = v.y;
    }
    float2 r = block_max2(mx, md);
    float sn2 = calc_sn(r.x);
    float sn1 = calc_sn(r.y);
    float inv1 = 1.0f / sn1, inv2 = 1.0f / sn2;   // exact (pow-2)

    int m0 = blockIdx.y * 32;
    int o0 = blockIdx.x * 32;
    int mm = threadIdx.x >> 3;          // staging row (m for x, o for W)
    int kg = (threadIdx.x & 7) << 3;    // staging k-offset (8 floats)
    int tx = threadIdx.x & 15;          // output o
    int ty = threadIdx.x >> 4;          // output m

    // float accumulator chains: integer-valued, stay in [2^23, 2^24) since
    // |running sum| <= 256*961 << 2^22. Each FFMA.RD adds exactly floor(a'*u').
    float f00 = BIGF, f01 = BIGF, f10 = BIGF, f11 = BIGF;
    int negcnt = 0;

    for (int kc = 0; kc < K_DIM; kc += BK) {
        // stage + conversion-free quantize (coalesced LDG.128, transposed STS)
        const float4* pa = (const float4*)&x[(m0 + mm) * K_DIM + kc + kg];
        const float4* pw = (const float4*)&W[(o0 + mm) * K_DIM + kc + kg];
        float4 aIn[2] = {pa[0], pa[1]};
        float4 wIn[2] = {pw[0], pw[1]};
        #pragma unroll
        for (int h = 0; h < 2; h++) {
            float av[4] = {aIn[h].x, aIn[h].y, aIn[h].z, aIn[h].w};
            float wv[4] = {wIn[h].x, wIn[h].y, wIn[h].z, wIn[h].w};
            #pragma unroll
            for (int e = 0; e < 4; e++) {
                int j = 4 * h + e;
                // x: t = RN(x*sn2) >= 0 ; floor(t) exactly via FADD.RD magic
                float t  = san(av[e]) * sn2;
                float fl = __fadd_rd(t, BIGF) - BIGF;
                s_a[kg + j][mm] = fl + THETA;
                // W: tw = RN(w*sn1) ; |bb| = floor(|tw|) ; sign/EPSB via selects
                float tw = san(wv[e]) * sn1;
                float ab = __fadd_rd(fabsf(tw), BIGF) - BIGF;
                bool  isneg = (tw < 0.0f) && (ab > 0.0f);
                float us = ab * (1.0f / 32.0f);
                us = (tw < 0.0f) ? -us : us;
                if (isneg) { us -= EPSB; negcnt++; }
                s_u[kg + j][mm] = us;
            }
        }
        __syncthreads();

        #pragma unroll 16
        for (int k = 0; k < BK; k++) {
            float2 a2 = *reinterpret_cast<const float2*>(&s_a[k][2 * ty]);
            float2 u2 = *reinterpret_cast<const float2*>(&s_u[k][2 * tx]);
            f00 = __fmaf_rd(a2.x, u2.x, f00);
            f01 = __fmaf_rd(a2.x, u2.y, f01);
            f10 = __fmaf_rd(a2.y, u2.x, f10);
            f11 = __fmaf_rd(a2.y, u2.y, f11);
        }
        __syncthreads();
    }

    // per-o negative count over full K (8 consecutive lanes share o-row mm)
    #pragma unroll
    for (int off = 1; off < 8; off <<= 1)
        negcnt += __shfl_xor_sync(0xFFFFFFFFu, negcnt, off);
    if ((threadIdx.x & 7) == 0) s_neg[mm] = negcnt;
    __syncthreads();

    // epilogue: x9 = (bits(f) - K*... ) handled per-acc: S = bits(f) - BIGU + N_o
    // d = trunc(x9 * 1/sn2) + cc ; out = d * 1/sn1 (all exact pow-2 ops)
    int m = m0 + 2 * ty;
    int o = o0 + 2 * tx;
    int n0 = s_neg[2 * tx], n1 = s_neg[2 * tx + 1];
    int c0 = (int)(san(b[o])     * sn1);
    int c1 = (int)(san(b[o + 1]) * sn1);

    int x900 = (int)(__float_as_uint(f00) - BIGU) + n0;
    int x901 = (int)(__float_as_uint(f01) - BIGU) + n1;
    int x910 = (int)(__float_as_uint(f10) - BIGU) + n0;
    int x911 = (int)(__float_as_uint(f11) - BIGU) + n1;

    float2 r0, r1;
    r0.x = (float)((int)((float)x900 * inv2) + c0) * inv1;
    r0.y = (float)((int)((float)x901 * inv2) + c1) * inv1;
    r1.x = (float)((int)((float)x910 * inv2) + c0) * inv1;
    r1.y = (float)((int)((float)x911 * inv2) + c1) * inv1;

    *reinterpret_cast<float2*>(&out[m * O_DIM + o])       = r0;
    *reinterpret_cast<float2*>(&out[(m + 1) * O_DIM + o]) = r1;
}

// ---------------- launch ----------------
extern "C" void kernel_launch(void* const* d_in, const int* in_sizes, int n_in,
                              void* d_out, int out_size) {
    (void)in_sizes; (void)n_in; (void)out_size;
    const float* x = (const float*)d_in[0];
    const float* W = (const float*)d_in[1];
    const float* b = (const float*)d_in[2];
    // d_in[3] (lut) unused: lut[i][j] == floor(i*j/32), reproduced exactly by
    // chained FFMA.RD magic-floor accumulation.

    reduce_kernel<<<RBLK, 256>>>(x, W, b);
    dim3 grid(O_DIM / 32, M_DIM / 32);
    fused_kernel<<<grid, 256>>>(x, W, b, (float*)d_out);
}